// round 6
// baseline (speedup 1.0000x reference)
#include <cuda_runtime.h>
#include <cuda_bf16.h>

// out[g, :] = sum over rows r with batch[r]==g of x[r, :]
// (softmax over a size-1 axis == 1.0 -> W, b mathematically dead).
// x: [N, 128] fp32, batch: [N] int32 SORTED, out: [G=10000, 128] fp32.
//
// Inputs identified BY ELEMENT COUNT (robust to metadata ordering):
//   x = unique largest (N*128), batch = unique with N elems.
//
// Segment-ownership design: ONE WARP PER SEGMENT g.
//   - binary search segment bounds in sorted batch (L2-resident, tree top
//     shared across all warps -> cached probes)
//   - stream the segment's rows (coalesced 512B/row, 4 independent
//     accumulators for MLP)
//   - exactly-once plain STG.128 write of out[g,:] (covers empty segments
//     with zeros -> no zero-fill pass, no atomics, single launch)

#define C    128
#define WPB  8                       // warps per block

__global__ __launch_bounds__(32 * WPB)
void segown_kernel(const float4* __restrict__ x4,   // [N, 32] float4 view
                   const int*    __restrict__ batch,// [N] int32 sorted
                   float4*       __restrict__ out4, // [G, 32] float4 view
                   int N, int G) {
    const int g = blockIdx.x * WPB + (threadIdx.x >> 5);
    if (g >= G) return;
    const int lane = threadIdx.x & 31;

    // lower_bound: first i with batch[i] >= g   (warp-uniform scalar search)
    int lo = 0, hi = N;
    while (lo < hi) {
        int mid = (lo + hi) >> 1;
        if (__ldg(&batch[mid]) < g) lo = mid + 1; else hi = mid;
    }
    const int start = lo;
    // lower_bound for g+1, starting from 'start'
    hi = N;
    while (lo < hi) {
        int mid = (lo + hi) >> 1;
        if (__ldg(&batch[mid]) < g + 1) lo = mid + 1; else hi = mid;
    }
    const int cnt = lo - start;

    float4 a0 = make_float4(0.f, 0.f, 0.f, 0.f);
    float4 a1 = a0, a2 = a0, a3 = a0;
    const float4* p = x4 + (size_t)start * (C / 4) + lane;

    int i = 0;
    for (; i + 4 <= cnt; i += 4) {           // 4 independent loads in flight
        float4 v0 = __ldg(p);
        float4 v1 = __ldg(p + 32);
        float4 v2 = __ldg(p + 64);
        float4 v3 = __ldg(p + 96);
        a0.x += v0.x; a0.y += v0.y; a0.z += v0.z; a0.w += v0.w;
        a1.x += v1.x; a1.y += v1.y; a1.z += v1.z; a1.w += v1.w;
        a2.x += v2.x; a2.y += v2.y; a2.z += v2.z; a2.w += v2.w;
        a3.x += v3.x; a3.y += v3.y; a3.z += v3.z; a3.w += v3.w;
        p += 128;
    }
    for (; i < cnt; ++i) {
        float4 v = __ldg(p);
        a0.x += v.x; a0.y += v.y; a0.z += v.z; a0.w += v.w;
        p += 32;
    }

    float4 s;
    s.x = (a0.x + a1.x) + (a2.x + a3.x);
    s.y = (a0.y + a1.y) + (a2.y + a3.y);
    s.z = (a0.z + a1.z) + (a2.z + a3.z);
    s.w = (a0.w + a1.w) + (a2.w + a3.w);

    out4[(size_t)g * (C / 4) + lane] = s;    // exactly-once write (zeros if empty)
}

extern "C" void kernel_launch(void* const* d_in, const int* in_sizes, int n_in,
                              void* d_out, int out_size) {
    // identify inputs by element count
    int xi = 0;
    long long best = -1;
    for (int i = 0; i < n_in; ++i)
        if ((long long)in_sizes[i] > best) { best = in_sizes[i]; xi = i; }
    const int N = in_sizes[xi] / C;
    int bi = -1;
    for (int i = 0; i < n_in; ++i)
        if (i != xi && in_sizes[i] == N) { bi = i; break; }
    if (bi < 0) bi = (xi == 1) ? 0 : 1;

    const float* x     = (const float*)d_in[xi];
    const int*   batch = (const int*)d_in[bi];
    const int G = out_size / C;

    dim3 block(32 * WPB);
    int grid = (G + WPB - 1) / WPB;
    segown_kernel<<<grid, block>>>((const float4*)x, batch, (float4*)d_out, N, G);
}

// round 7
// speedup vs baseline: 1.0185x; 1.0185x over previous
#include <cuda_runtime.h>
#include <cuda_bf16.h>

// out[g, :] = sum over rows r with batch[r]==g of x[r, :]
// (softmax over a size-1 axis == 1.0 -> W, b mathematically dead).
// x: [N, 128] fp32, batch: [N] int32 SORTED, out: [10000, 128] fp32.
//
// Inputs identified BY ELEMENT COUNT (robust to metadata ordering):
//   x = unique largest (N*128), batch = unique with N elems.
//
// R3 design (best measured profile: 73% DRAM, occ 81%, regs 32):
// each warp owns 64 contiguous rows x 128 cols (float4/lane); register
// run-length accumulate on the sorted ids, flush via red.global.add.v4.f32
// at segment boundaries. Zero-fill pass is the R4 float4 version.

#define C            128
#define TX           32          // lanes: 32 x float4 = 128 cols
#define TY           8           // warps per block
#define ROWS_PER_CHUNK 64        // contiguous rows per warp
#define ROWS_PER_BLOCK (TY * ROWS_PER_CHUNK)  // 512

__device__ __forceinline__ void red_add_v4(float* addr, float4 v) {
    asm volatile("red.global.add.v4.f32 [%0], {%1, %2, %3, %4};"
                 :: "l"(addr), "f"(v.x), "f"(v.y), "f"(v.z), "f"(v.w)
                 : "memory");
}

__global__ void zero_out_kernel(float4* __restrict__ out, int n4) {
    int i = blockIdx.x * blockDim.x + threadIdx.x;
    if (i < n4) out[i] = make_float4(0.f, 0.f, 0.f, 0.f);
}

__global__ __launch_bounds__(TX * TY)
void segsum_kernel(const float4* __restrict__ x4,     // [N, 32] float4 view
                   const int* __restrict__ batch,     // [N] int32 sorted
                   float* __restrict__ out,           // [G, 128]
                   int N, int G) {
    const int tx = threadIdx.x;      // 0..31  -> column group (float4)
    const int ty = threadIdx.y;      // 0..7   -> warp / row chunk

    int r0 = blockIdx.x * ROWS_PER_BLOCK + ty * ROWS_PER_CHUNK;
    if (r0 >= N) return;
    int rend = r0 + ROWS_PER_CHUNK;
    if (rend > N) rend = N;

    float4 acc = make_float4(0.f, 0.f, 0.f, 0.f);
    int cur = __ldg(&batch[r0]);        // uniform across warp -> broadcast

    #pragma unroll 4
    for (int r = r0; r < rend; ++r) {
        int b = __ldg(&batch[r]);               // uniform broadcast load
        float4 v = __ldg(&x4[(size_t)r * (C / 4) + tx]);
        if (b != cur) {
            int g = min(max(cur, 0), G - 1);    // defensive clamp (no-op if sane)
            red_add_v4(out + (size_t)g * C + tx * 4, acc);
            acc = make_float4(0.f, 0.f, 0.f, 0.f);
            cur = b;
        }
        acc.x += v.x; acc.y += v.y; acc.z += v.z; acc.w += v.w;
    }
    int g = min(max(cur, 0), G - 1);
    red_add_v4(out + (size_t)g * C + tx * 4, acc);
}

extern "C" void kernel_launch(void* const* d_in, const int* in_sizes, int n_in,
                              void* d_out, int out_size) {
    // --- identify inputs by element count (robust to metadata ordering) ---
    int xi = 0;
    long long best = -1;
    for (int i = 0; i < n_in; ++i) {
        if ((long long)in_sizes[i] > best) { best = in_sizes[i]; xi = i; }
    }
    const int N = in_sizes[xi] / C;          // rows of x
    int bi = -1;
    for (int i = 0; i < n_in; ++i) {
        if (i != xi && in_sizes[i] == N) { bi = i; break; }
    }
    if (bi < 0) bi = (xi == 1) ? 0 : 1;      // fallback (shouldn't happen)

    const float* x     = (const float*)d_in[xi];   // [N,128] fp32
    const int*   batch = (const int*)d_in[bi];     // [N] int32 sorted
    float* out = (float*)d_out;
    const int G = out_size / C;

    // d_out is poisoned to 0xAA — zero it first (vectorized, same stream).
    int n4 = out_size / 4;
    zero_out_kernel<<<(n4 + 255) / 256, 256>>>((float4*)out, n4);

    dim3 block(TX, TY);
    int grid = (N + ROWS_PER_BLOCK - 1) / ROWS_PER_BLOCK;
    segsum_kernel<<<grid, block>>>((const float4*)x, batch, out, N, G);
}

// round 8
// speedup vs baseline: 1.0877x; 1.0680x over previous
#include <cuda_runtime.h>
#include <cuda_bf16.h>

// out[g, :] = sum over rows r with batch[r]==g of x[r, :]
// (softmax over a size-1 axis == 1.0 -> W, b mathematically dead).
// x: [N, 128] fp32, batch: [N] int32 SORTED, out: [10000, 128] fp32.
//
// Inputs identified BY ELEMENT COUNT (robust to metadata ordering):
//   x = unique largest (N*128), batch = unique with N elems.
//
// R7 segsum (best measured: 73.5% DRAM, occ 83%, regs 32) + memset prologue:
// each warp owns 64 contiguous rows x 128 cols (float4/lane); register
// run-length accumulate on sorted ids, flush via red.global.add.v4.f32 at
// segment boundaries. x loads use __ldcs (streaming, zero reuse).
// Zero-fill is a cudaMemsetAsync graph node (cheaper than a kernel launch).

#define C            128
#define TX           32          // lanes: 32 x float4 = 128 cols
#define TY           8           // warps per block
#define ROWS_PER_CHUNK 64        // contiguous rows per warp
#define ROWS_PER_BLOCK (TY * ROWS_PER_CHUNK)  // 512

__device__ __forceinline__ void red_add_v4(float* addr, float4 v) {
    asm volatile("red.global.add.v4.f32 [%0], {%1, %2, %3, %4};"
                 :: "l"(addr), "f"(v.x), "f"(v.y), "f"(v.z), "f"(v.w)
                 : "memory");
}

__global__ __launch_bounds__(TX * TY)
void segsum_kernel(const float4* __restrict__ x4,     // [N, 32] float4 view
                   const int* __restrict__ batch,     // [N] int32 sorted
                   float* __restrict__ out,           // [G, 128]
                   int N, int G) {
    const int tx = threadIdx.x;      // 0..31  -> column group (float4)
    const int ty = threadIdx.y;      // 0..7   -> warp / row chunk

    int r0 = blockIdx.x * ROWS_PER_BLOCK + ty * ROWS_PER_CHUNK;
    if (r0 >= N) return;
    int rend = r0 + ROWS_PER_CHUNK;
    if (rend > N) rend = N;

    float4 acc = make_float4(0.f, 0.f, 0.f, 0.f);
    int cur = __ldg(&batch[r0]);        // uniform across warp -> broadcast

    #pragma unroll 4
    for (int r = r0; r < rend; ++r) {
        int b = __ldg(&batch[r]);               // uniform broadcast load
        float4 v = __ldcs(&x4[(size_t)r * (C / 4) + tx]);  // streaming load
        if (b != cur) {
            int g = min(max(cur, 0), G - 1);    // defensive clamp (no-op if sane)
            red_add_v4(out + (size_t)g * C + tx * 4, acc);
            acc = make_float4(0.f, 0.f, 0.f, 0.f);
            cur = b;
        }
        acc.x += v.x; acc.y += v.y; acc.z += v.z; acc.w += v.w;
    }
    int g = min(max(cur, 0), G - 1);
    red_add_v4(out + (size_t)g * C + tx * 4, acc);
}

extern "C" void kernel_launch(void* const* d_in, const int* in_sizes, int n_in,
                              void* d_out, int out_size) {
    // --- identify inputs by element count (robust to metadata ordering) ---
    int xi = 0;
    long long best = -1;
    for (int i = 0; i < n_in; ++i) {
        if ((long long)in_sizes[i] > best) { best = in_sizes[i]; xi = i; }
    }
    const int N = in_sizes[xi] / C;          // rows of x
    int bi = -1;
    for (int i = 0; i < n_in; ++i) {
        if (i != xi && in_sizes[i] == N) { bi = i; break; }
    }
    if (bi < 0) bi = (xi == 1) ? 0 : 1;      // fallback (shouldn't happen)

    const float* x     = (const float*)d_in[xi];   // [N,128] fp32
    const int*   batch = (const int*)d_in[bi];     // [N] int32 sorted
    float* out = (float*)d_out;
    const int G = out_size / C;

    // Zero the poisoned output: graph-capturable memset node (cheaper than
    // a zero-fill kernel launch; atomics below depend on it, same stream).
    cudaMemsetAsync(out, 0, (size_t)out_size * sizeof(float));

    dim3 block(TX, TY);
    int grid = (N + ROWS_PER_BLOCK - 1) / ROWS_PER_BLOCK;
    segsum_kernel<<<grid, block>>>((const float4*)x, batch, out, N, G);
}